// round 1
// baseline (speedup 1.0000x reference)
#include <cuda_runtime.h>
#include <cuda_fp16.h>

#define BB 64
#define NN 1024
#define DD 256
#define HH 256
#define TH3 768
#define NTYPES 300
#define AW_ROWS 1300   // 300 type rows + 1000 pos rows

// Persistent scratch (static device globals: no allocation at runtime)
__device__ float        g_AW[AW_ROWS * TH3];      // [type_emb;pos_table] @ w_ih^T  (~4MB)
__device__ unsigned int g_whhp[128 * TH3];        // w_hh packed half2, layout [k2][row]
__device__ int          g_prog[128];              // per-CTA progress counters

// ---------------------------------------------------------------------------
__global__ void init_prog_kernel() {
    if (threadIdx.x < 128) g_prog[threadIdx.x] = 0;
}

// ---------------------------------------------------------------------------
// g_AW[m][r] = dot(A_m, w_ih[r,:]),  A = concat(type_emb, pos_table), K=256
// grid (ceil(1300/64)=21, 768/64=12), 256 threads, 4x4 micro-tile
__global__ void aw_gemm_kernel(const float* __restrict__ te,
                               const float* __restrict__ pe,
                               const float* __restrict__ wih) {
    __shared__ float As[16][64];
    __shared__ float Ws[16][68];
    const int tx = threadIdx.x & 15;
    const int ty = threadIdx.x >> 4;
    float acc[4][4] = {};
    for (int kt = 0; kt < 256; kt += 16) {
        int row = threadIdx.x >> 2;
        int kk  = (threadIdx.x & 3) * 4;
        int m   = blockIdx.x * 64 + row;
        float4 av = make_float4(0.f, 0.f, 0.f, 0.f);
        if (m < AW_ROWS) {
            const float* ap = (m < NTYPES) ? (te + (size_t)m * 256)
                                           : (pe + (size_t)(m - NTYPES) * 256);
            av = *(const float4*)(ap + kt + kk);
        }
        As[kk + 0][row] = av.x; As[kk + 1][row] = av.y;
        As[kk + 2][row] = av.z; As[kk + 3][row] = av.w;
        float4 wv = *(const float4*)(wih + (size_t)(blockIdx.y * 64 + row) * 256 + kt + kk);
        Ws[kk + 0][row] = wv.x; Ws[kk + 1][row] = wv.y;
        Ws[kk + 2][row] = wv.z; Ws[kk + 3][row] = wv.w;
        __syncthreads();
#pragma unroll
        for (int k = 0; k < 16; k++) {
            float a[4], w[4];
#pragma unroll
            for (int i = 0; i < 4; i++) { a[i] = As[k][ty * 4 + i]; w[i] = Ws[k][tx * 4 + i]; }
#pragma unroll
            for (int i = 0; i < 4; i++)
#pragma unroll
                for (int j = 0; j < 4; j++)
                    acc[i][j] = fmaf(a[i], w[j], acc[i][j]);
        }
        __syncthreads();
    }
#pragma unroll
    for (int i = 0; i < 4; i++) {
        int m = blockIdx.x * 64 + ty * 4 + i;
        if (m < AW_ROWS) {
#pragma unroll
            for (int j = 0; j < 4; j++)
                g_AW[(size_t)m * TH3 + blockIdx.y * 64 + tx * 4 + j] = acc[i][j];
        }
    }
}

// ---------------------------------------------------------------------------
// Pack w_hh (fp32 [768,256]) -> half2, transposed layout [k2=128][row=768]
__global__ void pack_whh_kernel(const float* __restrict__ whh) {
    int idx = blockIdx.x * 256 + threadIdx.x;
    if (idx < 768 * 128) {
        int r  = idx % 768;
        int k2 = idx / 768;
        __half2 h2 = __floats2half2_rn(whh[(size_t)r * 256 + 2 * k2],
                                       whh[(size_t)r * 256 + 2 * k2 + 1]);
        g_whhp[k2 * 768 + r] = *(unsigned int*)&h2;
    }
}

// ---------------------------------------------------------------------------
// out[n][b][0:256] = 4*te[type] + 0.25*pos[cp] + 4*mean(token_emb[bag])
// grid 16384 blocks x 256 threads; each block = 4 bags, 64 lanes of float4 each
__global__ void embed_out_kernel(const int* __restrict__ types,
                                 const int* __restrict__ vals,
                                 const int* __restrict__ offs,
                                 const int* __restrict__ cps,
                                 const float* __restrict__ te,
                                 const float* __restrict__ pe,
                                 const float* __restrict__ tok,
                                 float* __restrict__ out, int L) {
    int sub  = threadIdx.x >> 6;
    int lane = threadIdx.x & 63;
    int j = blockIdx.x * 4 + sub;             // bag id in [0, 65536)
    int b = j >> 10, n = j & 1023;
    int tt  = types[j];
    int cp  = cps[j];
    int off = offs[j];
    int offn = (j + 1 < BB * NN) ? offs[j + 1] : L;
    float cnt = (float)((offn - off) > 1 ? (offn - off) : 1);
    float4 s = make_float4(0.f, 0.f, 0.f, 0.f);
    for (int v = off; v < offn; v++) {
        float4 t = ((const float4*)tok)[(size_t)vals[v] * 64 + lane];
        s.x += t.x; s.y += t.y; s.z += t.z; s.w += t.w;
    }
    float4 tev = ((const float4*)te)[(size_t)tt * 64 + lane];
    float4 pev = ((const float4*)pe)[(size_t)cp * 64 + lane];
    float inv = 4.0f / cnt;
    float4 r;
    r.x = 4.f * tev.x + 0.25f * pev.x + s.x * inv;
    r.y = 4.f * tev.y + 0.25f * pev.y + s.y * inv;
    r.z = 4.f * tev.z + 0.25f * pev.z + s.z * inv;
    r.w = 4.f * tev.w + 0.25f * pev.w + s.w * inv;
    ((float4*)out)[((size_t)n * 64 + b) * 128 + lane] = r;
}

// ---------------------------------------------------------------------------
// Persistent GRU scan. 128 CTAs = 2 per batch chain (hh = which half of the
// 256 hidden units). Each CTA owns 384 rows of w_hh ({j, 256+j, 512+j} for its
// 128 j's) resident in SMEM as fp16. Pair CTAs lockstep via g_prog flags.
// Hidden states live directly in out[:, :, 256:512].
#define GRU_SMEM (128 * 384 * 4 + 256 * 4 + 768 * 4 + 384 * 4 + 384 * 4)

__global__ void __launch_bounds__(768, 1)
gru_kernel(const int* __restrict__ lpi_all, const int* __restrict__ types,
           const int* __restrict__ cps, const float* __restrict__ bih,
           const float* __restrict__ bhh, float* __restrict__ out) {
    extern __shared__ unsigned char smem_raw[];
    unsigned int* w_s = (unsigned int*)smem_raw;            // [128][384]
    float* h_s  = (float*)(smem_raw + 128 * 384 * 4);       // 256
    float* part = h_s + 256;                                // 768
    float* gi_s = part + 768;                               // 384
    float* gh_s = gi_s + 384;                               // 384

    const int tid  = threadIdx.x;
    const int cid  = blockIdx.x;
    const int b    = cid >> 1;
    const int hh   = cid & 1;
    const int peer = cid ^ 1;
    const int half = (tid >= 384) ? 1 : 0;   // k-split: which half of K
    const int r    = tid - half * 384;       // local row 0..383
    const int g    = r >> 7;                 // gate 0=r,1=z,2=n
    const int jl   = r & 127;
    const int gr   = g * 256 + hh * 128 + jl;  // global row in [0,768)

    // Load this CTA's weight slice: w_s[k2][rr] for its 384 rows
    for (int idx = tid; idx < 128 * 384; idx += 768) {
        int k2 = idx / 384, rr = idx - k2 * 384;
        int gg = rr >> 7, jj = rr & 127;
        w_s[idx] = g_whhp[k2 * 768 + gg * 256 + hh * 128 + jj];
    }
    float bih_r = 0.f, bhh_r = 0.f;
    if (half == 0) { bih_r = bih[gr]; bhh_r = bhh[gr]; }
    __syncthreads();

    const int* lpi_b = lpi_all + b * NN;
    const int* ty_b  = types + b * NN;
    const int* cp_b  = cps + b * NN;
    const int k0 = half * 64;
    const float* aw_pe = g_AW + (size_t)NTYPES * TH3;

    for (int i = 0; i < NN; i++) {
        // gi for my rows (independent of peer — do before the sync)
        if (half == 0) {
            int tt = ty_b[i], cp = cp_b[i];
            gi_s[r] = 4.0f * g_AW[(size_t)tt * TH3 + gr]
                    + 0.25f * aw_pe[(size_t)cp * TH3 + gr] + bih_r;
        }
        if (i > 0) {
            if (tid == 0) {
                while (*((volatile int*)(g_prog + peer)) < i) { }
                __threadfence();
            }
            __syncthreads();
            int lpi = lpi_b[i];
            if (tid < 256)
                h_s[tid] = out[((size_t)lpi * 64 + b) * 512 + 256 + tid];
        } else {
            if (tid < 256) h_s[tid] = 0.f;
        }
        __syncthreads();

        // gemv: my row, my half of K (64 half2 pairs)
        float acc = 0.f;
        const float2* h2 = (const float2*)h_s;
#pragma unroll 8
        for (int k2 = 0; k2 < 64; k2++) {
            unsigned int wb = w_s[(k0 + k2) * 384 + r];
            float2 wf = __half22float2(*(__half2*)&wb);
            float2 hv = h2[k0 + k2];
            acc = fmaf(wf.x, hv.x, acc);
            acc = fmaf(wf.y, hv.y, acc);
        }
        part[tid] = acc;
        __syncthreads();
        if (half == 0) gh_s[r] = part[r] + part[r + 384] + bhh_r;
        __syncthreads();

        if (tid < 128) {
            float rg = 1.f / (1.f + __expf(-(gi_s[jl] + gh_s[jl])));
            float zg = 1.f / (1.f + __expf(-(gi_s[128 + jl] + gh_s[128 + jl])));
            float ng = tanhf(gi_s[256 + jl] + rg * gh_s[256 + jl]);
            float hp = h_s[hh * 128 + jl];
            out[((size_t)i * 64 + b) * 512 + 256 + hh * 128 + jl] =
                (1.f - zg) * ng + zg * hp;
        }
        __syncthreads();
        if (tid == 0) {
            __threadfence();
            *((volatile int*)(g_prog + cid)) = i + 1;
        }
    }
}

// ---------------------------------------------------------------------------
extern "C" void kernel_launch(void* const* d_in, const int* in_sizes, int n_in,
                              void* d_out, int out_size) {
    const int*   node_types = (const int*)d_in[0];
    const int*   node_vals  = (const int*)d_in[1];
    const int*   node_off   = (const int*)d_in[2];
    const int*   lpi        = (const int*)d_in[3];
    const int*   child_pos  = (const int*)d_in[4];
    const float* type_emb   = (const float*)d_in[5];
    const float* pos_table  = (const float*)d_in[6];
    const float* token_emb  = (const float*)d_in[7];
    // d_in[8] = w_ih
    const float* w_ih       = (const float*)d_in[8];
    const float* w_hh       = (const float*)d_in[9];
    const float* b_ih       = (const float*)d_in[10];
    const float* b_hh       = (const float*)d_in[11];
    float* out = (float*)d_out;
    int L = in_sizes[1];

    static int smem_set = 0;
    if (!smem_set) {
        cudaFuncSetAttribute(gru_kernel, cudaFuncAttributeMaxDynamicSharedMemorySize,
                             GRU_SMEM);
        smem_set = 1;
    }

    init_prog_kernel<<<1, 128>>>();
    aw_gemm_kernel<<<dim3(21, 12), 256>>>(type_emb, pos_table, w_ih);
    pack_whh_kernel<<<384, 256>>>(w_hh);
    embed_out_kernel<<<16384, 256>>>(node_types, node_vals, node_off, child_pos,
                                     type_emb, pos_table, token_emb, out, L);
    gru_kernel<<<128, 768, GRU_SMEM>>>(lpi, node_types, child_pos, b_ih, b_hh, out);
}

// round 4
// speedup vs baseline: 1.3919x; 1.3919x over previous
#include <cuda_runtime.h>
#include <cuda_fp16.h>

#define BB 64
#define NN 1024
#define DD 256
#define HH 256
#define TH3 768
#define NTYPES 300
#define AW_ROWS 1300   // 300 type rows + 1000 pos rows

// Persistent scratch (static device globals: no allocation at runtime)
__device__ float        g_AW[AW_ROWS * TH3];      // [type_emb;pos_table] @ w_ih^T  (~4MB)
__device__ unsigned int g_whhp[TH3 * 128];        // w_hh packed half2, layout [row][k2]
__device__ int          g_prog[128];              // per-CTA progress counters

__device__ __forceinline__ int ld_acquire_gpu(const int* p) {
    int v;
    asm volatile("ld.acquire.gpu.b32 %0, [%1];" : "=r"(v) : "l"(p) : "memory");
    return v;
}
__device__ __forceinline__ void st_release_gpu(int* p, int v) {
    asm volatile("st.release.gpu.b32 [%0], %1;" :: "l"(p), "r"(v) : "memory");
}
__device__ __forceinline__ float tanh_fast(float x) {
    float y;
    asm("tanh.approx.f32 %0, %1;" : "=f"(y) : "f"(x));
    return y;
}

// ---------------------------------------------------------------------------
__global__ void init_prog_kernel() {
    if (threadIdx.x < 128) g_prog[threadIdx.x] = 0;
}

// ---------------------------------------------------------------------------
// g_AW[m][r] = dot(A_m, w_ih[r,:]),  A = concat(type_emb, pos_table), K=256
__global__ void aw_gemm_kernel(const float* __restrict__ te,
                               const float* __restrict__ pe,
                               const float* __restrict__ wih) {
    __shared__ float As[16][64];
    __shared__ float Ws[16][68];
    const int tx = threadIdx.x & 15;
    const int ty = threadIdx.x >> 4;
    float acc[4][4] = {};
    for (int kt = 0; kt < 256; kt += 16) {
        int row = threadIdx.x >> 2;
        int kk  = (threadIdx.x & 3) * 4;
        int m   = blockIdx.x * 64 + row;
        float4 av = make_float4(0.f, 0.f, 0.f, 0.f);
        if (m < AW_ROWS) {
            const float* ap = (m < NTYPES) ? (te + (size_t)m * 256)
                                           : (pe + (size_t)(m - NTYPES) * 256);
            av = *(const float4*)(ap + kt + kk);
        }
        As[kk + 0][row] = av.x; As[kk + 1][row] = av.y;
        As[kk + 2][row] = av.z; As[kk + 3][row] = av.w;
        float4 wv = *(const float4*)(wih + (size_t)(blockIdx.y * 64 + row) * 256 + kt + kk);
        Ws[kk + 0][row] = wv.x; Ws[kk + 1][row] = wv.y;
        Ws[kk + 2][row] = wv.z; Ws[kk + 3][row] = wv.w;
        __syncthreads();
#pragma unroll
        for (int k = 0; k < 16; k++) {
            float a[4], w[4];
#pragma unroll
            for (int i = 0; i < 4; i++) { a[i] = As[k][ty * 4 + i]; w[i] = Ws[k][tx * 4 + i]; }
#pragma unroll
            for (int i = 0; i < 4; i++)
#pragma unroll
                for (int j = 0; j < 4; j++)
                    acc[i][j] = fmaf(a[i], w[j], acc[i][j]);
        }
        __syncthreads();
    }
#pragma unroll
    for (int i = 0; i < 4; i++) {
        int m = blockIdx.x * 64 + ty * 4 + i;
        if (m < AW_ROWS) {
#pragma unroll
            for (int j = 0; j < 4; j++)
                g_AW[(size_t)m * TH3 + blockIdx.y * 64 + tx * 4 + j] = acc[i][j];
        }
    }
}

// ---------------------------------------------------------------------------
// Pack w_hh (fp32 [768,256]) -> half2, layout [row][k2]
__global__ void pack_whh_kernel(const float* __restrict__ whh) {
    int idx = blockIdx.x * 256 + threadIdx.x;
    if (idx < 768 * 128) {
        int r  = idx >> 7;
        int k2 = idx & 127;
        __half2 h2 = __floats2half2_rn(whh[(size_t)r * 256 + 2 * k2],
                                       whh[(size_t)r * 256 + 2 * k2 + 1]);
        g_whhp[r * 128 + k2] = *(unsigned int*)&h2;
    }
}

// ---------------------------------------------------------------------------
// out[n][b][0:256] = 4*te[type] + 0.25*pos[cp] + 4*mean(token_emb[bag])
__global__ void embed_out_kernel(const int* __restrict__ types,
                                 const int* __restrict__ vals,
                                 const int* __restrict__ offs,
                                 const int* __restrict__ cps,
                                 const float* __restrict__ te,
                                 const float* __restrict__ pe,
                                 const float* __restrict__ tok,
                                 float* __restrict__ out, int L) {
    int sub  = threadIdx.x >> 6;
    int lane = threadIdx.x & 63;
    int j = blockIdx.x * 4 + sub;             // bag id in [0, 65536)
    int b = j >> 10, n = j & 1023;
    int tt  = types[j];
    int cp  = cps[j];
    int off = offs[j];
    int offn = (j + 1 < BB * NN) ? offs[j + 1] : L;
    float cnt = (float)((offn - off) > 1 ? (offn - off) : 1);
    float4 s = make_float4(0.f, 0.f, 0.f, 0.f);
    for (int v = off; v < offn; v++) {
        float4 t = ((const float4*)tok)[(size_t)vals[v] * 64 + lane];
        s.x += t.x; s.y += t.y; s.z += t.z; s.w += t.w;
    }
    float4 tev = ((const float4*)te)[(size_t)tt * 64 + lane];
    float4 pev = ((const float4*)pe)[(size_t)cp * 64 + lane];
    float inv = 4.0f / cnt;
    float4 r;
    r.x = 4.f * tev.x + 0.25f * pev.x + s.x * inv;
    r.y = 4.f * tev.y + 0.25f * pev.y + s.y * inv;
    r.z = 4.f * tev.z + 0.25f * pev.z + s.z * inv;
    r.w = 4.f * tev.w + 0.25f * pev.w + s.w * inv;
    ((float4*)out)[((size_t)n * 64 + b) * 128 + lane] = r;
}

// ---------------------------------------------------------------------------
// Persistent GRU scan v2.
// 128 CTAs = 2 per batch chain (hh = which half of the 256 hidden units).
// 384 threads/CTA, one w_hh row per thread, full K=256 per thread.
// Weights half2 in SMEM (padded rows, conflict-free LDS.128); gemv in HFMA2
// with 8 rotating half2 accumulators; h converted to half2 once per step.
// Pair CTAs sync ONLY on the parent dependency: wait peer_prog > lpi[i]
// (lpi < i, so the wait is rarely binding).
#define W_STRIDE 132                       // uints per row (128 + 4 pad)
#define SM_W     (384 * W_STRIDE * 4)      // 202752
#define SM_H     SM_W                      // h_s: 256 floats
#define SM_H2    (SM_H + 1024)             // h2_s: 128 uints
#define SM_PRE   (SM_H2 + 512)             // pre_s: 384 floats
#define SM_GHN   (SM_PRE + 1536)           // ghn_s: 128 floats
#define GRU_SMEM (SM_GHN + 512)            // 206336 bytes

__global__ void __launch_bounds__(384, 1)
gru_kernel(const int* __restrict__ lpi_all, const int* __restrict__ types,
           const int* __restrict__ cps, const float* __restrict__ bih,
           const float* __restrict__ bhh, float* __restrict__ out) {
    extern __shared__ unsigned char smem_raw[];
    unsigned int* w_s   = (unsigned int*)smem_raw;           // [384][W_STRIDE]
    float*        h_s   = (float*)(smem_raw + SM_H);         // 256 (fp32 parent h)
    unsigned int* h2_s  = (unsigned int*)(smem_raw + SM_H2); // 128 half2
    float*        pre_s = (float*)(smem_raw + SM_PRE);       // 384
    float*        ghn_s = (float*)(smem_raw + SM_GHN);       // 128

    const int tid  = threadIdx.x;
    const int cid  = blockIdx.x;
    const int b    = cid >> 1;
    const int hh   = cid & 1;
    const int peer = cid ^ 1;
    const int r    = tid;                    // local row 0..383
    const int g    = r >> 7;                 // gate 0=r,1=z,2=n
    const int jl   = r & 127;
    const int gr   = g * 256 + hh * 128 + jl;  // global w_hh row in [0,768)

    // Load this CTA's weight slice into padded smem rows
    for (int idx = tid; idx < 384 * 128; idx += 384) {
        int rr = idx >> 7, k2 = idx & 127;
        int gg = rr >> 7, jj = rr & 127;
        w_s[rr * W_STRIDE + k2] = g_whhp[(gg * 256 + hh * 128 + jj) * 128 + k2];
    }
    const float bih_r = bih[gr];
    const float bhh_r = bhh[gr];
    __syncthreads();

    const int* lpi_b = lpi_all + b * NN;
    const int* ty_b  = types + b * NN;
    const int* cp_b  = cps + b * NN;
    const float* aw_pe = g_AW + (size_t)NTYPES * TH3;
    const unsigned int* wr = w_s + r * W_STRIDE;

    int peer_seen = 0;

    for (int i = 0; i < NN; i++) {
        // gi for my row (independent of parent — issue L2 loads early)
        int tt = ty_b[i], cp = cp_b[i];
        float giv = fmaf(4.0f, g_AW[(size_t)tt * TH3 + gr],
                    fmaf(0.25f, aw_pe[(size_t)cp * TH3 + gr], bih_r));

        // threads 0..63: fetch parent hidden (full 256 floats) after the
        // (rarely binding) dependency wait on the peer CTA's progress
        if (tid < 64) {
            float4 hv = make_float4(0.f, 0.f, 0.f, 0.f);
            if (i > 0) {
                int lpi = lpi_b[i];
                if (peer_seen <= lpi) {
                    int v;
                    do { v = ld_acquire_gpu(g_prog + peer); } while (v <= lpi);
                    peer_seen = v;
                }
                hv = *(const float4*)(out + ((size_t)lpi * 64 + b) * 512 + 256 + tid * 4);
            }
            *(float4*)(h_s + tid * 4) = hv;
            __half2 p0 = __floats2half2_rn(hv.x, hv.y);
            __half2 p1 = __floats2half2_rn(hv.z, hv.w);
            h2_s[tid * 2 + 0] = *(unsigned int*)&p0;
            h2_s[tid * 2 + 1] = *(unsigned int*)&p1;
        }
        __syncthreads();

        // gemv: 32 x (LDS.128 w + LDS.128 h2 + 4 HFMA2), 8 rotating accumulators
        __half2 acc[8];
#pragma unroll
        for (int k = 0; k < 8; k++) acc[k] = __floats2half2_rn(0.f, 0.f);
        const uint4* w4p = (const uint4*)wr;
        const uint4* h4p = (const uint4*)h2_s;
#pragma unroll
        for (int j = 0; j < 32; j++) {
            uint4 wv = w4p[j];
            uint4 hv = h4p[j];
            int base = (j & 1) * 4;
            acc[base + 0] = __hfma2(*(__half2*)&wv.x, *(__half2*)&hv.x, acc[base + 0]);
            acc[base + 1] = __hfma2(*(__half2*)&wv.y, *(__half2*)&hv.y, acc[base + 1]);
            acc[base + 2] = __hfma2(*(__half2*)&wv.z, *(__half2*)&hv.z, acc[base + 2]);
            acc[base + 3] = __hfma2(*(__half2*)&wv.w, *(__half2*)&hv.w, acc[base + 3]);
        }
        float2 s0 = __half22float2(acc[0]);
        float2 s1 = __half22float2(acc[1]);
        float2 s2 = __half22float2(acc[2]);
        float2 s3 = __half22float2(acc[3]);
        float2 s4 = __half22float2(acc[4]);
        float2 s5 = __half22float2(acc[5]);
        float2 s6 = __half22float2(acc[6]);
        float2 s7 = __half22float2(acc[7]);
        float gh = ((s0.x + s0.y) + (s1.x + s1.y)) + ((s2.x + s2.y) + (s3.x + s3.y))
                 + ((s4.x + s4.y) + (s5.x + s5.y)) + ((s6.x + s6.y) + (s7.x + s7.y))
                 + bhh_r;

        if (r < 256) {
            pre_s[r] = giv + gh;           // r/z gates: gi+gh ready for sigmoid
        } else {
            pre_s[r] = giv;                // n gate: keep separate (needs rg*ghn)
            ghn_s[jl] = gh;
        }
        __syncthreads();

        if (tid < 128) {
            float rg = 1.0f / (1.0f + __expf(-pre_s[tid]));
            float zg = 1.0f / (1.0f + __expf(-pre_s[128 + tid]));
            float ng = tanh_fast(fmaf(rg, ghn_s[tid], pre_s[256 + tid]));
            float hp = h_s[hh * 128 + tid];
            // (1-z)*n + z*h = n + z*(h-n)
            out[((size_t)i * 64 + b) * 512 + 256 + hh * 128 + tid] =
                fmaf(zg, hp - ng, ng);
        }
        __syncthreads();
        if (tid == 0) {
            __threadfence();
            st_release_gpu(g_prog + cid, i + 1);
        }
    }
}

// ---------------------------------------------------------------------------
extern "C" void kernel_launch(void* const* d_in, const int* in_sizes, int n_in,
                              void* d_out, int out_size) {
    const int*   node_types = (const int*)d_in[0];
    const int*   node_vals  = (const int*)d_in[1];
    const int*   node_off   = (const int*)d_in[2];
    const int*   lpi        = (const int*)d_in[3];
    const int*   child_pos  = (const int*)d_in[4];
    const float* type_emb   = (const float*)d_in[5];
    const float* pos_table  = (const float*)d_in[6];
    const float* token_emb  = (const float*)d_in[7];
    const float* w_ih       = (const float*)d_in[8];
    const float* w_hh       = (const float*)d_in[9];
    const float* b_ih       = (const float*)d_in[10];
    const float* b_hh       = (const float*)d_in[11];
    float* out = (float*)d_out;
    int L = in_sizes[1];

    static int smem_set = 0;
    if (!smem_set) {
        cudaFuncSetAttribute(gru_kernel, cudaFuncAttributeMaxDynamicSharedMemorySize,
                             GRU_SMEM);
        smem_set = 1;
    }

    init_prog_kernel<<<1, 128>>>();
    aw_gemm_kernel<<<dim3(21, 12), 256>>>(type_emb, pos_table, w_ih);
    pack_whh_kernel<<<384, 256>>>(w_hh);
    embed_out_kernel<<<16384, 256>>>(node_types, node_vals, node_off, child_pos,
                                     type_emb, pos_table, token_emb, out, L);
    gru_kernel<<<128, 384, GRU_SMEM>>>(lpi, node_types, child_pos, b_ih, b_hh, out);
}

// round 9
// speedup vs baseline: 2.3037x; 1.6550x over previous
#include <cuda_runtime.h>
#include <cuda_fp16.h>

#define BB 64
#define NN 1024
#define TH3 768
#define NTYPES 300
#define AW_ROWS 1300

// ---- persistent device scratch (no runtime allocation) ----
__device__ float        g_AW[AW_ROWS * TH3];     // [type_emb;pos_table] @ w_ih^T
__device__ unsigned int g_whhp[TH3 * 128];       // w_hh half2, [row][k2]
__device__ int          g_depth[BB * NN];
__device__ int          g_cnt[BB * NN];          // [b][d]
__device__ int          g_batch_base[NN * BB];   // [d][b]
__device__ int          g_wave_off[NN + 1];
__device__ int          g_order[BB * NN];        // (i<<6)|b sorted by depth
__device__ int          g_nwaves;
__device__ int          g_bar_cnt;
__device__ int          g_bar_epoch;

__device__ __forceinline__ int ld_acquire_gpu(const int* p) {
    int v;
    asm volatile("ld.acquire.gpu.b32 %0, [%1];" : "=r"(v) : "l"(p) : "memory");
    return v;
}
__device__ __forceinline__ void st_release_gpu(int* p, int v) {
    asm volatile("st.release.gpu.b32 [%0], %1;" :: "l"(p), "r"(v) : "memory");
}
__device__ __forceinline__ float tanh_fast(float x) {
    float y;
    asm("tanh.approx.f32 %0, %1;" : "=f"(y) : "f"(x));
    return y;
}
__device__ __forceinline__ float sigmoid_fast(float x) {
    return 1.0f / (1.0f + __expf(-x));
}

// ---------------------------------------------------------------------------
__global__ void init_misc_kernel() {
    if (threadIdx.x == 0) { g_bar_cnt = 0; g_bar_epoch = 0; }
}

// ---------------------------------------------------------------------------
// g_AW[m][r] = dot(A_m, w_ih[r,:]),  A = concat(type_emb, pos_table), K=256
__global__ void aw_gemm_kernel(const float* __restrict__ te,
                               const float* __restrict__ pe,
                               const float* __restrict__ wih) {
    __shared__ float As[16][64];
    __shared__ float Ws[16][68];
    const int tx = threadIdx.x & 15;
    const int ty = threadIdx.x >> 4;
    float acc[4][4] = {};
    for (int kt = 0; kt < 256; kt += 16) {
        int row = threadIdx.x >> 2;
        int kk  = (threadIdx.x & 3) * 4;
        int m   = blockIdx.x * 64 + row;
        float4 av = make_float4(0.f, 0.f, 0.f, 0.f);
        if (m < AW_ROWS) {
            const float* ap = (m < NTYPES) ? (te + (size_t)m * 256)
                                           : (pe + (size_t)(m - NTYPES) * 256);
            av = *(const float4*)(ap + kt + kk);
        }
        As[kk + 0][row] = av.x; As[kk + 1][row] = av.y;
        As[kk + 2][row] = av.z; As[kk + 3][row] = av.w;
        float4 wv = *(const float4*)(wih + (size_t)(blockIdx.y * 64 + row) * 256 + kt + kk);
        Ws[kk + 0][row] = wv.x; Ws[kk + 1][row] = wv.y;
        Ws[kk + 2][row] = wv.z; Ws[kk + 3][row] = wv.w;
        __syncthreads();
#pragma unroll
        for (int k = 0; k < 16; k++) {
            float a[4], w[4];
#pragma unroll
            for (int i = 0; i < 4; i++) { a[i] = As[k][ty * 4 + i]; w[i] = Ws[k][tx * 4 + i]; }
#pragma unroll
            for (int i = 0; i < 4; i++)
#pragma unroll
                for (int j = 0; j < 4; j++)
                    acc[i][j] = fmaf(a[i], w[j], acc[i][j]);
        }
        __syncthreads();
    }
#pragma unroll
    for (int i = 0; i < 4; i++) {
        int m = blockIdx.x * 64 + ty * 4 + i;
        if (m < AW_ROWS) {
#pragma unroll
            for (int j = 0; j < 4; j++)
                g_AW[(size_t)m * TH3 + blockIdx.y * 64 + tx * 4 + j] = acc[i][j];
        }
    }
}

// ---------------------------------------------------------------------------
__global__ void pack_whh_kernel(const float* __restrict__ whh) {
    int idx = blockIdx.x * 256 + threadIdx.x;
    if (idx < 768 * 128) {
        int r  = idx >> 7;
        int k2 = idx & 127;
        __half2 h2 = __floats2half2_rn(whh[(size_t)r * 256 + 2 * k2],
                                       whh[(size_t)r * 256 + 2 * k2 + 1]);
        g_whhp[r * 128 + k2] = *(unsigned int*)&h2;
    }
}

// ---------------------------------------------------------------------------
__global__ void embed_out_kernel(const int* __restrict__ types,
                                 const int* __restrict__ vals,
                                 const int* __restrict__ offs,
                                 const int* __restrict__ cps,
                                 const float* __restrict__ te,
                                 const float* __restrict__ pe,
                                 const float* __restrict__ tok,
                                 float* __restrict__ out, int L) {
    int sub  = threadIdx.x >> 6;
    int lane = threadIdx.x & 63;
    int j = blockIdx.x * 4 + sub;
    int b = j >> 10, n = j & 1023;
    int tt  = types[j];
    int cp  = cps[j];
    int off = offs[j];
    int offn = (j + 1 < BB * NN) ? offs[j + 1] : L;
    float cnt = (float)((offn - off) > 1 ? (offn - off) : 1);
    float4 s = make_float4(0.f, 0.f, 0.f, 0.f);
    for (int v = off; v < offn; v++) {
        float4 t = ((const float4*)tok)[(size_t)vals[v] * 64 + lane];
        s.x += t.x; s.y += t.y; s.z += t.z; s.w += t.w;
    }
    float4 tev = ((const float4*)te)[(size_t)tt * 64 + lane];
    float4 pev = ((const float4*)pe)[(size_t)cp * 64 + lane];
    float inv = 4.0f / cnt;
    float4 r;
    r.x = 4.f * tev.x + 0.25f * pev.x + s.x * inv;
    r.y = 4.f * tev.y + 0.25f * pev.y + s.y * inv;
    r.z = 4.f * tev.z + 0.25f * pev.z + s.z * inv;
    r.w = 4.f * tev.w + 0.25f * pev.w + s.w * inv;
    ((float4*)out)[((size_t)n * 64 + b) * 128 + lane] = r;
}

// ---------------------------------------------------------------------------
// P1: per-batch node depth via wavefront relaxation + per-depth counts
__global__ void prep_depth_kernel(const int* __restrict__ lpi_all) {
    __shared__ int lpi_s[NN];
    __shared__ int dep_s[NN];
    __shared__ int cnt_s[NN];
    __shared__ int remain;
    int b = blockIdx.x, tid = threadIdx.x;
    for (int i = tid; i < NN; i += 128) {
        lpi_s[i] = lpi_all[b * NN + i];
        dep_s[i] = (i == 0) ? 0 : -1;
        cnt_s[i] = 0;
    }
    if (tid == 0) remain = NN - 1;
    __syncthreads();
    while (true) {
        if (remain == 0) break;
        int solved = 0;
        for (int i = tid; i < NN; i += 128) {
            if (dep_s[i] < 0) {
                int d = dep_s[lpi_s[i]];
                if (d >= 0) { dep_s[i] = d + 1; solved++; }
            }
        }
        __syncthreads();
        if (solved) atomicAdd(&remain, -solved);
        __syncthreads();
    }
    for (int i = tid; i < NN; i += 128) {
        atomicAdd(&cnt_s[dep_s[i]], 1);
        g_depth[b * NN + i] = dep_s[i];
    }
    __syncthreads();
    for (int d = tid; d < NN; d += 128) g_cnt[b * NN + d] = cnt_s[d];
}

// P2: per-depth batch prefixes + wave offsets + wave count
__global__ void prep_offsets_kernel() {
    __shared__ int tot_s[NN];
    int d = threadIdx.x;
    int base = 0;
    for (int b = 0; b < BB; b++) {
        g_batch_base[d * BB + b] = base;
        base += g_cnt[b * NN + d];
    }
    tot_s[d] = base;
    __syncthreads();
    if (d == 0) {
        int acc = 0, maxd = 0;
        for (int x = 0; x < NN; x++) {
            g_wave_off[x] = acc;
            acc += tot_s[x];
            if (tot_s[x] > 0) maxd = x;
        }
        g_wave_off[NN] = acc;
        g_nwaves = maxd + 1;
    }
}

// P3: scatter nodes into wave order
__global__ void prep_scatter_kernel() {
    __shared__ int cur_s[NN];
    __shared__ int dep_s[NN];
    int b = blockIdx.x, tid = threadIdx.x;
    for (int d = tid; d < NN; d += 128)
        cur_s[d] = g_wave_off[d] + g_batch_base[d * BB + b];
    for (int i = tid; i < NN; i += 128)
        dep_s[i] = g_depth[b * NN + i];
    __syncthreads();
    if (tid == 0) {
        for (int i = 0; i < NN; i++) {
            int d = dep_s[i];
            g_order[cur_s[d]++] = (i << 6) | b;
        }
    }
}

// ---------------------------------------------------------------------------
// Wave GRU kernel: persistent 148 CTAs, one depth-wave at a time.
// Tile: M=64 nodes x N=768 rows x K=256. 512 threads; thread = 4 nodes x
// (2 hidden units x 3 gates). Weights streamed L2->smem per 192-row chunk,
// HFMA2 with fp32 flush every 64 k-elements. Epilogue fuses gi gathers
// (g_AW), gates, and h store into out[:,:,256:512].
#define SM_W   0                      // w_s:  192*132 uints = 101376 B
#define SM_H2  101376                 // h2_s:  64*132 uints =  33792 B
#define SM_HF  135168                 // h_s:   64*260 floats =  66560 B
#define SM_ND  201728                 // node ids (64 ints)
#define SM_TS  201984
#define SM_CP  202240
#define WAVE_SMEM 202496
#define NCTA 148

__global__ void __launch_bounds__(512, 1)
wave_gru_kernel(const int* __restrict__ lpi_all, const int* __restrict__ types,
                const int* __restrict__ cps, const float* __restrict__ bih,
                const float* __restrict__ bhh, float* __restrict__ out) {
    extern __shared__ unsigned char smem[];
    unsigned int* w_s  = (unsigned int*)(smem + SM_W);
    unsigned int* h2_s = (unsigned int*)(smem + SM_H2);
    float*        h_s  = (float*)(smem + SM_HF);
    int*          nd_s = (int*)(smem + SM_ND);
    int*          ts_s = (int*)(smem + SM_TS);
    int*          cp_s = (int*)(smem + SM_CP);

    const int tid = threadIdx.x;
    const int tx  = tid & 31;
    const int ty  = tid >> 5;
    const int nwaves = g_nwaves;
    const float* aw_pe = g_AW + (size_t)NTYPES * TH3;

    for (int w = 0; w < nwaves; w++) {
        int ms = g_wave_off[w];
        int me = g_wave_off[w + 1];
        int ntiles = (me - ms + 63) >> 6;

        for (int t = blockIdx.x; t < ntiles; t += gridDim.x) {
            int base = ms + (t << 6);
            int Mrem = me - base; if (Mrem > 64) Mrem = 64;

            __syncthreads();
            if (tid < 64) {
                int ordv = -1, tt = 0, cpv = 0;
                if (tid < Mrem) {
                    ordv = g_order[base + tid];
                    int bb = ordv & 63, ii = ordv >> 6;
                    tt  = types[bb * NN + ii];
                    cpv = cps[bb * NN + ii];
                }
                nd_s[tid] = ordv; ts_s[tid] = tt; cp_s[tid] = cpv;
            }
            __syncthreads();

            // gather parent hidden states: 8 threads per node, 32 floats each
            {
                int m = tid >> 3, seg = tid & 7;
                int ordv = nd_s[m];
                float4 v[8];
#pragma unroll
                for (int q = 0; q < 8; q++) v[q] = make_float4(0.f, 0.f, 0.f, 0.f);
                if (ordv >= 0) {
                    int bb = ordv & 63, ii = ordv >> 6;
                    if (ii > 0) {
                        int lp = lpi_all[bb * NN + ii];
                        const float4* src = (const float4*)(out +
                            (((size_t)lp * 64 + bb) * 512 + 256));
#pragma unroll
                        for (int q = 0; q < 8; q++) v[q] = src[seg * 8 + q];
                    }
                }
                float*        hd  = h_s  + m * 260 + seg * 32;
                unsigned int* h2d = h2_s + m * 132 + seg * 16;
#pragma unroll
                for (int q = 0; q < 8; q++) {
                    *(float4*)(hd + q * 4) = v[q];
                    __half2 a = __floats2half2_rn(v[q].x, v[q].y);
                    __half2 b2 = __floats2half2_rn(v[q].z, v[q].w);
                    h2d[q * 2 + 0] = *(unsigned int*)&a;
                    h2d[q * 2 + 1] = *(unsigned int*)&b2;
                }
            }

            // 4 chunks of 64 hidden units (192 rows = 64 units x 3 gates)
            for (int c = 0; c < 4; c++) {
                __syncthreads();
                // cooperative weight load: 192 rows x 32 uint4, permuted slots
                {
                    const uint4* src = (const uint4*)g_whhp;
#pragma unroll
                    for (int it = 0; it < 12; it++) {
                        int flat = tid + it * 512;       // 0..6143
                        int slot = flat >> 5;            // 0..191
                        int kq   = flat & 31;
                        int g    = slot >> 6;
                        int wi   = slot & 63;
                        int j    = ((wi & 31) << 1) | (wi >> 5);
                        int grow = g * 256 + c * 64 + j;
                        uint4 val = src[grow * 32 + kq];
                        *(uint4*)(w_s + slot * 132 + kq * 4) = val;
                    }
                }
                __syncthreads();

                float   facc[4][6];
                __half2 hacc[4][6];
#pragma unroll
                for (int n = 0; n < 4; n++)
#pragma unroll
                    for (int r = 0; r < 6; r++) {
                        facc[n][r] = 0.f;
                        hacc[n][r] = __floats2half2_rn(0.f, 0.f);
                    }

                const uint4* hp0 = (const uint4*)(h2_s + (4 * ty + 0) * 132);
                const uint4* hp1 = (const uint4*)(h2_s + (4 * ty + 1) * 132);
                const uint4* hp2 = (const uint4*)(h2_s + (4 * ty + 2) * 132);
                const uint4* hp3 = (const uint4*)(h2_s + (4 * ty + 3) * 132);
                const uint4* wp[6];
#pragma unroll
                for (int g = 0; g < 3; g++)
#pragma unroll
                    for (int uu = 0; uu < 2; uu++)
                        wp[g * 2 + uu] = (const uint4*)(w_s + (g * 64 + tx + uu * 32) * 132);

#define DO4(n, r, HV, WV)                                                            \
    hacc[n][r] = __hfma2(*(__half2*)&(WV).x, *(__half2*)&(HV).x, hacc[n][r]);        \
    hacc[n][r] = __hfma2(*(__half2*)&(WV).y, *(__half2*)&(HV).y, hacc[n][r]);        \
    hacc[n][r] = __hfma2(*(__half2*)&(WV).z, *(__half2*)&(HV).z, hacc[n][r]);        \
    hacc[n][r] = __hfma2(*(__half2*)&(WV).w, *(__half2*)&(HV).w, hacc[n][r]);

#pragma unroll
                for (int q = 0; q < 32; q++) {
                    uint4 hv0 = hp0[q], hv1 = hp1[q], hv2 = hp2[q], hv3 = hp3[q];
                    uint4 wv0 = wp[0][q], wv1 = wp[1][q], wv2 = wp[2][q];
                    uint4 wv3 = wp[3][q], wv4 = wp[4][q], wv5 = wp[5][q];
                    DO4(0, 0, hv0, wv0) DO4(0, 1, hv0, wv1) DO4(0, 2, hv0, wv2)
                    DO4(0, 3, hv0, wv3) DO4(0, 4, hv0, wv4) DO4(0, 5, hv0, wv5)
                    DO4(1, 0, hv1, wv0) DO4(1, 1, hv1, wv1) DO4(1, 2, hv1, wv2)
                    DO4(1, 3, hv1, wv3) DO4(1, 4, hv1, wv4) DO4(1, 5, hv1, wv5)
                    DO4(2, 0, hv2, wv0) DO4(2, 1, hv2, wv1) DO4(2, 2, hv2, wv2)
                    DO4(2, 3, hv2, wv3) DO4(2, 4, hv2, wv4) DO4(2, 5, hv2, wv5)
                    DO4(3, 0, hv3, wv0) DO4(3, 1, hv3, wv1) DO4(3, 2, hv3, wv2)
                    DO4(3, 3, hv3, wv3) DO4(3, 4, hv3, wv4) DO4(3, 5, hv3, wv5)
                    if ((q & 7) == 7) {
#pragma unroll
                        for (int n = 0; n < 4; n++)
#pragma unroll
                            for (int r = 0; r < 6; r++) {
                                float2 f = __half22float2(hacc[n][r]);
                                facc[n][r] += f.x + f.y;
                                hacc[n][r] = __floats2half2_rn(0.f, 0.f);
                            }
                    }
                }
#undef DO4

                // epilogue: gates + store for this chunk's 64 units
#pragma unroll
                for (int n = 0; n < 4; n++) {
                    int m = 4 * ty + n;
                    if (m >= Mrem) continue;
                    int ordv = nd_s[m];
                    int bb = ordv & 63, ii = ordv >> 6;
                    int tt = ts_s[m], cpv = cp_s[m];
                    const float* awt = g_AW + (size_t)tt * TH3;
                    const float* awp = aw_pe + (size_t)cpv * TH3;
                    float hnew[2];
#pragma unroll
                    for (int uu = 0; uu < 2; uu++) {
                        int u  = c * 64 + 2 * tx + uu;
                        int r0 = u, r1 = 256 + u, r2 = 512 + u;
                        float gi_r = fmaf(4.f, awt[r0], fmaf(0.25f, awp[r0], bih[r0]));
                        float gi_z = fmaf(4.f, awt[r1], fmaf(0.25f, awp[r1], bih[r1]));
                        float gi_n = fmaf(4.f, awt[r2], fmaf(0.25f, awp[r2], bih[r2]));
                        float gh_r = facc[n][0 + uu] + bhh[r0];
                        float gh_z = facc[n][2 + uu] + bhh[r1];
                        float gh_n = facc[n][4 + uu] + bhh[r2];
                        float rg = sigmoid_fast(gi_r + gh_r);
                        float zg = sigmoid_fast(gi_z + gh_z);
                        float ng = tanh_fast(fmaf(rg, gh_n, gi_n));
                        float hp = h_s[m * 260 + u];
                        hnew[uu] = fmaf(zg, hp - ng, ng);
                    }
                    *(float2*)(out + ((size_t)ii * 64 + bb) * 512 + 256 + c * 64 + 2 * tx) =
                        make_float2(hnew[0], hnew[1]);
                }
            } // chunks
        } // tiles

        // global wave barrier
        if (tid == 0) {
            __threadfence();
            int a = atomicAdd(&g_bar_cnt, 1);
            if (a == gridDim.x - 1) {
                atomicExch(&g_bar_cnt, 0);
                st_release_gpu(&g_bar_epoch, w + 1);
            } else {
                while (ld_acquire_gpu(&g_bar_epoch) < w + 1) { }
            }
        }
        __syncthreads();
    }
}

// ---------------------------------------------------------------------------
extern "C" void kernel_launch(void* const* d_in, const int* in_sizes, int n_in,
                              void* d_out, int out_size) {
    const int*   node_types = (const int*)d_in[0];
    const int*   node_vals  = (const int*)d_in[1];
    const int*   node_off   = (const int*)d_in[2];
    const int*   lpi        = (const int*)d_in[3];
    const int*   child_pos  = (const int*)d_in[4];
    const float* type_emb   = (const float*)d_in[5];
    const float* pos_table  = (const float*)d_in[6];
    const float* token_emb  = (const float*)d_in[7];
    const float* w_ih       = (const float*)d_in[8];
    const float* w_hh       = (const float*)d_in[9];
    const float* b_ih       = (const float*)d_in[10];
    const float* b_hh       = (const float*)d_in[11];
    float* out = (float*)d_out;
    int L = in_sizes[1];

    static int smem_set = 0;
    if (!smem_set) {
        cudaFuncSetAttribute(wave_gru_kernel,
                             cudaFuncAttributeMaxDynamicSharedMemorySize, WAVE_SMEM);
        smem_set = 1;
    }

    init_misc_kernel<<<1, 32>>>();
    aw_gemm_kernel<<<dim3(21, 12), 256>>>(type_emb, pos_table, w_ih);
    pack_whh_kernel<<<384, 256>>>(w_hh);
    prep_depth_kernel<<<64, 128>>>(lpi);
    prep_offsets_kernel<<<1, 1024>>>();
    prep_scatter_kernel<<<64, 128>>>();
    embed_out_kernel<<<16384, 256>>>(node_types, node_vals, node_off, child_pos,
                                     type_emb, pos_table, token_emb, out, L);
    wave_gru_kernel<<<NCTA, 512, WAVE_SMEM>>>(lpi, node_types, child_pos,
                                              b_ih, b_hh, out);
}

// round 11
// speedup vs baseline: 4.3747x; 1.8990x over previous
#include <cuda_runtime.h>
#include <cuda_fp16.h>

#define BB 64
#define NN 1024
#define TH3 768
#define NTYPES 300
#define AW_ROWS 1300

// ---- persistent device scratch (no runtime allocation) ----
__device__ float        g_AW[AW_ROWS * TH3];     // [type_emb;pos_table] @ w_ih^T
__device__ unsigned int g_whhp[TH3 * 128];       // w_hh half2, [row][k2]
__device__ int          g_depth[BB * NN];
__device__ int          g_cnt[BB * NN];          // [b][d]
__device__ int          g_batch_base[NN * BB];   // [d][b]
__device__ int          g_wave_off[NN + 1];
__device__ int          g_order[BB * NN];        // (i<<6)|b sorted by depth
__device__ int          g_nwaves;
__device__ int          g_bar_cnt;
__device__ int          g_bar_epoch;

__device__ __forceinline__ int ld_acquire_gpu(const int* p) {
    int v;
    asm volatile("ld.acquire.gpu.b32 %0, [%1];" : "=r"(v) : "l"(p) : "memory");
    return v;
}
__device__ __forceinline__ void st_release_gpu(int* p, int v) {
    asm volatile("st.release.gpu.b32 [%0], %1;" :: "l"(p), "r"(v) : "memory");
}
__device__ __forceinline__ float tanh_fast(float x) {
    float y;
    asm("tanh.approx.f32 %0, %1;" : "=f"(y) : "f"(x));
    return y;
}
__device__ __forceinline__ float sigmoid_fast(float x) {
    return 1.0f / (1.0f + __expf(-x));
}

// ---------------------------------------------------------------------------
__global__ void init_misc_kernel() {
    if (threadIdx.x == 0) { g_bar_cnt = 0; g_bar_epoch = 0; }
}

// ---------------------------------------------------------------------------
// g_AW[m][r] = dot(A_m, w_ih[r,:]),  A = concat(type_emb, pos_table), K=256
__global__ void aw_gemm_kernel(const float* __restrict__ te,
                               const float* __restrict__ pe,
                               const float* __restrict__ wih) {
    __shared__ float As[16][64];
    __shared__ float Ws[16][68];
    const int tx = threadIdx.x & 15;
    const int ty = threadIdx.x >> 4;
    float acc[4][4] = {};
    for (int kt = 0; kt < 256; kt += 16) {
        int row = threadIdx.x >> 2;
        int kk  = (threadIdx.x & 3) * 4;
        int m   = blockIdx.x * 64 + row;
        float4 av = make_float4(0.f, 0.f, 0.f, 0.f);
        if (m < AW_ROWS) {
            const float* ap = (m < NTYPES) ? (te + (size_t)m * 256)
                                           : (pe + (size_t)(m - NTYPES) * 256);
            av = *(const float4*)(ap + kt + kk);
        }
        As[kk + 0][row] = av.x; As[kk + 1][row] = av.y;
        As[kk + 2][row] = av.z; As[kk + 3][row] = av.w;
        float4 wv = *(const float4*)(wih + (size_t)(blockIdx.y * 64 + row) * 256 + kt + kk);
        Ws[kk + 0][row] = wv.x; Ws[kk + 1][row] = wv.y;
        Ws[kk + 2][row] = wv.z; Ws[kk + 3][row] = wv.w;
        __syncthreads();
#pragma unroll
        for (int k = 0; k < 16; k++) {
            float a[4], w[4];
#pragma unroll
            for (int i = 0; i < 4; i++) { a[i] = As[k][ty * 4 + i]; w[i] = Ws[k][tx * 4 + i]; }
#pragma unroll
            for (int i = 0; i < 4; i++)
#pragma unroll
                for (int j = 0; j < 4; j++)
                    acc[i][j] = fmaf(a[i], w[j], acc[i][j]);
        }
        __syncthreads();
    }
#pragma unroll
    for (int i = 0; i < 4; i++) {
        int m = blockIdx.x * 64 + ty * 4 + i;
        if (m < AW_ROWS) {
#pragma unroll
            for (int j = 0; j < 4; j++)
                g_AW[(size_t)m * TH3 + blockIdx.y * 64 + tx * 4 + j] = acc[i][j];
        }
    }
}

// ---------------------------------------------------------------------------
__global__ void pack_whh_kernel(const float* __restrict__ whh) {
    int idx = blockIdx.x * 256 + threadIdx.x;
    if (idx < 768 * 128) {
        int r  = idx >> 7;
        int k2 = idx & 127;
        __half2 h2 = __floats2half2_rn(whh[(size_t)r * 256 + 2 * k2],
                                       whh[(size_t)r * 256 + 2 * k2 + 1]);
        g_whhp[r * 128 + k2] = *(unsigned int*)&h2;
    }
}

// ---------------------------------------------------------------------------
__global__ void embed_out_kernel(const int* __restrict__ types,
                                 const int* __restrict__ vals,
                                 const int* __restrict__ offs,
                                 const int* __restrict__ cps,
                                 const float* __restrict__ te,
                                 const float* __restrict__ pe,
                                 const float* __restrict__ tok,
                                 float* __restrict__ out, int L) {
    int sub  = threadIdx.x >> 6;
    int lane = threadIdx.x & 63;
    int j = blockIdx.x * 4 + sub;
    int b = j >> 10, n = j & 1023;
    int tt  = types[j];
    int cp  = cps[j];
    int off = offs[j];
    int offn = (j + 1 < BB * NN) ? offs[j + 1] : L;
    float cnt = (float)((offn - off) > 1 ? (offn - off) : 1);
    float4 s = make_float4(0.f, 0.f, 0.f, 0.f);
    for (int v = off; v < offn; v++) {
        float4 t = ((const float4*)tok)[(size_t)vals[v] * 64 + lane];
        s.x += t.x; s.y += t.y; s.z += t.z; s.w += t.w;
    }
    float4 tev = ((const float4*)te)[(size_t)tt * 64 + lane];
    float4 pev = ((const float4*)pe)[(size_t)cp * 64 + lane];
    float inv = 4.0f / cnt;
    float4 r;
    r.x = 4.f * tev.x + 0.25f * pev.x + s.x * inv;
    r.y = 4.f * tev.y + 0.25f * pev.y + s.y * inv;
    r.z = 4.f * tev.z + 0.25f * pev.z + s.z * inv;
    r.w = 4.f * tev.w + 0.25f * pev.w + s.w * inv;
    ((float4*)out)[((size_t)n * 64 + b) * 128 + lane] = r;
}

// ---------------------------------------------------------------------------
// P1: per-batch node depth via wavefront relaxation + per-depth counts
__global__ void prep_depth_kernel(const int* __restrict__ lpi_all) {
    __shared__ int lpi_s[NN];
    __shared__ int dep_s[NN];
    __shared__ int cnt_s[NN];
    __shared__ int remain;
    int b = blockIdx.x, tid = threadIdx.x;
    for (int i = tid; i < NN; i += 128) {
        lpi_s[i] = lpi_all[b * NN + i];
        dep_s[i] = (i == 0) ? 0 : -1;
        cnt_s[i] = 0;
    }
    if (tid == 0) remain = NN - 1;
    __syncthreads();
    while (true) {
        if (remain == 0) break;
        int solved = 0;
        for (int i = tid; i < NN; i += 128) {
            if (dep_s[i] < 0) {
                int d = dep_s[lpi_s[i]];
                if (d >= 0) { dep_s[i] = d + 1; solved++; }
            }
        }
        __syncthreads();
        if (solved) atomicAdd(&remain, -solved);
        __syncthreads();
    }
    for (int i = tid; i < NN; i += 128) {
        atomicAdd(&cnt_s[dep_s[i]], 1);
        g_depth[b * NN + i] = dep_s[i];
    }
    __syncthreads();
    for (int d = tid; d < NN; d += 128) g_cnt[b * NN + d] = cnt_s[d];
}

// P2: per-depth batch prefixes + wave offsets + wave count
__global__ void prep_offsets_kernel() {
    __shared__ int tot_s[NN];
    int d = threadIdx.x;
    int base = 0;
    for (int b = 0; b < BB; b++) {
        g_batch_base[d * BB + b] = base;
        base += g_cnt[b * NN + d];
    }
    tot_s[d] = base;
    __syncthreads();
    if (d == 0) {
        int acc = 0, maxd = 0;
        for (int x = 0; x < NN; x++) {
            g_wave_off[x] = acc;
            acc += tot_s[x];
            if (tot_s[x] > 0) maxd = x;
        }
        g_wave_off[NN] = acc;
        g_nwaves = maxd + 1;
    }
}

// P3: scatter nodes into wave order
__global__ void prep_scatter_kernel() {
    __shared__ int cur_s[NN];
    __shared__ int dep_s[NN];
    int b = blockIdx.x, tid = threadIdx.x;
    for (int d = tid; d < NN; d += 128)
        cur_s[d] = g_wave_off[d] + g_batch_base[d * BB + b];
    for (int i = tid; i < NN; i += 128)
        dep_s[i] = g_depth[b * NN + i];
    __syncthreads();
    if (tid == 0) {
        for (int i = 0; i < NN; i++) {
            int d = dep_s[i];
            g_order[cur_s[d]++] = (i << 6) | b;
        }
    }
}

// ---------------------------------------------------------------------------
// Wave GRU v3: 148 persistent CTAs = 37 node-groups x 4 chunk-CTAs.
// Each CTA keeps its 192-row W_hh chunk (98KB half2) RESIDENT in smem for the
// whole kernel. Per wave: node tiles of M=64 (big waves) or M=16 (tail waves,
// W<=592) over N=192 (this CTA's chunk) x K=256. Gate epilogue fuses g_AW
// gathers, gates, and h store into out[:,:,256:512].
#define SM_W   0                      // w_s:  192*132 uints = 101376 B
#define SM_H2  101376                 // h2_s:  64*132 uints =  33792 B
#define SM_HF  135168                 // h_s:   64*260 floats =  66560 B
#define SM_ND  201728                 // node ids (64 ints)
#define SM_TS  201984
#define SM_CP  202240
#define WAVE_SMEM 202496
#define NCTA 148
#define NGRP 37

__global__ void __launch_bounds__(512, 1)
wave_gru_kernel(const int* __restrict__ lpi_all, const int* __restrict__ types,
                const int* __restrict__ cps, const float* __restrict__ bih,
                const float* __restrict__ bhh, float* __restrict__ out) {
    extern __shared__ unsigned char smem[];
    unsigned int* w_s  = (unsigned int*)(smem + SM_W);
    unsigned int* h2_s = (unsigned int*)(smem + SM_H2);
    float*        h_s  = (float*)(smem + SM_HF);
    int*          nd_s = (int*)(smem + SM_ND);
    int*          ts_s = (int*)(smem + SM_TS);
    int*          cp_s = (int*)(smem + SM_CP);

    const int tid = threadIdx.x;
    const int tx  = tid & 31;
    const int ty  = tid >> 5;
    const int c   = blockIdx.x & 3;       // chunk (64 hidden units) owned
    const int grp = blockIdx.x >> 2;      // node-group 0..36
    const int nwaves = g_nwaves;
    const float* aw_pe = g_AW + (size_t)NTYPES * TH3;

    // ---- load resident weight chunk once: 192 rows x 32 uint4, permuted ----
    {
        const uint4* src = (const uint4*)g_whhp;
#pragma unroll
        for (int it = 0; it < 12; it++) {
            int flat = tid + it * 512;       // 0..6143
            int slot = flat >> 5;            // 0..191
            int kq   = flat & 31;
            int g    = slot >> 6;
            int wi   = slot & 63;
            int j    = ((wi & 31) << 1) | (wi >> 5);
            int grow = g * 256 + c * 64 + j;
            *(uint4*)(w_s + slot * 132 + kq * 4) = src[grow * 32 + kq];
        }
    }
    // per-thread bias rows (fixed: rows g*256 + c*64 + 2*tx + uu)
    float bih_u[2][3], bhh_u[2][3];
#pragma unroll
    for (int uu = 0; uu < 2; uu++)
#pragma unroll
        for (int g = 0; g < 3; g++) {
            int rr = g * 256 + c * 64 + 2 * tx + uu;
            bih_u[uu][g] = bih[rr];
            bhh_u[uu][g] = bhh[rr];
        }
    const uint4* wp[6];
#pragma unroll
    for (int g = 0; g < 3; g++)
#pragma unroll
        for (int uu = 0; uu < 2; uu++)
            wp[g * 2 + uu] = (const uint4*)(w_s + (g * 64 + tx + uu * 32) * 132);

#define DO4H(ACC, HV, WV)                                                  \
    ACC = __hfma2(*(__half2*)&(WV).x, *(__half2*)&(HV).x, ACC);            \
    ACC = __hfma2(*(__half2*)&(WV).y, *(__half2*)&(HV).y, ACC);            \
    ACC = __hfma2(*(__half2*)&(WV).z, *(__half2*)&(HV).z, ACC);            \
    ACC = __hfma2(*(__half2*)&(WV).w, *(__half2*)&(HV).w, ACC);

    for (int w = 0; w < nwaves; w++) {
        int ms = g_wave_off[w];
        int me = g_wave_off[w + 1];
        int W  = me - ms;
        int big = (W > 592);
        int Msz = big ? 64 : 16;
        int ntiles = (W + Msz - 1) / Msz;

        for (int t = grp; t < ntiles; t += NGRP) {
            int base = ms + t * Msz;
            int Mrem = me - base; if (Mrem > Msz) Mrem = Msz;

            __syncthreads();
            if (tid < Msz) {
                int ordv = -1, tt = 0, cpv = 0;
                if (tid < Mrem) {
                    ordv = g_order[base + tid];
                    int bb = ordv & 63, ii = ordv >> 6;
                    tt  = types[bb * NN + ii];
                    cpv = cps[bb * NN + ii];
                }
                nd_s[tid] = ordv; ts_s[tid] = tt; cp_s[tid] = cpv;
            }
            __syncthreads();

            // ---- gather parent hidden states + half2 convert ----
            if (big) {
                // 8 threads/node, 32 floats each
                int m = tid >> 3, seg = tid & 7;
                int ordv = nd_s[m];
                float4 v[8];
#pragma unroll
                for (int q = 0; q < 8; q++) v[q] = make_float4(0.f, 0.f, 0.f, 0.f);
                if (ordv >= 0) {
                    int bb = ordv & 63, ii = ordv >> 6;
                    if (ii > 0) {
                        int lp = lpi_all[bb * NN + ii];
                        const float4* src = (const float4*)(out +
                            (((size_t)lp * 64 + bb) * 512 + 256));
#pragma unroll
                        for (int q = 0; q < 8; q++) v[q] = src[seg * 8 + q];
                    }
                }
                float*        hd  = h_s  + m * 260 + seg * 32;
                unsigned int* h2d = h2_s + m * 132 + seg * 16;
#pragma unroll
                for (int q = 0; q < 8; q++) {
                    *(float4*)(hd + q * 4) = v[q];
                    __half2 a  = __floats2half2_rn(v[q].x, v[q].y);
                    __half2 b2 = __floats2half2_rn(v[q].z, v[q].w);
                    h2d[q * 2 + 0] = *(unsigned int*)&a;
                    h2d[q * 2 + 1] = *(unsigned int*)&b2;
                }
            } else {
                // 32 threads/node, 8 floats each
                int m = tid >> 5, seg = tid & 31;
                int ordv = nd_s[m];
                float4 v[2];
                v[0] = make_float4(0.f, 0.f, 0.f, 0.f);
                v[1] = v[0];
                if (ordv >= 0) {
                    int bb = ordv & 63, ii = ordv >> 6;
                    if (ii > 0) {
                        int lp = lpi_all[bb * NN + ii];
                        const float4* src = (const float4*)(out +
                            (((size_t)lp * 64 + bb) * 512 + 256));
                        v[0] = src[seg * 2]; v[1] = src[seg * 2 + 1];
                    }
                }
                float*        hd  = h_s  + m * 260 + seg * 8;
                unsigned int* h2d = h2_s + m * 132 + seg * 4;
#pragma unroll
                for (int q = 0; q < 2; q++) {
                    *(float4*)(hd + q * 4) = v[q];
                    __half2 a  = __floats2half2_rn(v[q].x, v[q].y);
                    __half2 b2 = __floats2half2_rn(v[q].z, v[q].w);
                    h2d[q * 2 + 0] = *(unsigned int*)&a;
                    h2d[q * 2 + 1] = *(unsigned int*)&b2;
                }
            }
            __syncthreads();

            if (big) {
                // ---- M=64 gemv: thread = 4 nodes x 6 rows ----
                float   facc[4][6];
                __half2 hacc[4][6];
#pragma unroll
                for (int n = 0; n < 4; n++)
#pragma unroll
                    for (int r = 0; r < 6; r++) {
                        facc[n][r] = 0.f;
                        hacc[n][r] = __floats2half2_rn(0.f, 0.f);
                    }
                const uint4* hp0 = (const uint4*)(h2_s + (4 * ty + 0) * 132);
                const uint4* hp1 = (const uint4*)(h2_s + (4 * ty + 1) * 132);
                const uint4* hp2 = (const uint4*)(h2_s + (4 * ty + 2) * 132);
                const uint4* hp3 = (const uint4*)(h2_s + (4 * ty + 3) * 132);
#pragma unroll
                for (int q = 0; q < 32; q++) {
                    uint4 hv0 = hp0[q], hv1 = hp1[q], hv2 = hp2[q], hv3 = hp3[q];
                    uint4 wv0 = wp[0][q], wv1 = wp[1][q], wv2 = wp[2][q];
                    uint4 wv3 = wp[3][q], wv4 = wp[4][q], wv5 = wp[5][q];
                    DO4H(hacc[0][0], hv0, wv0) DO4H(hacc[0][1], hv0, wv1)
                    DO4H(hacc[0][2], hv0, wv2) DO4H(hacc[0][3], hv0, wv3)
                    DO4H(hacc[0][4], hv0, wv4) DO4H(hacc[0][5], hv0, wv5)
                    DO4H(hacc[1][0], hv1, wv0) DO4H(hacc[1][1], hv1, wv1)
                    DO4H(hacc[1][2], hv1, wv2) DO4H(hacc[1][3], hv1, wv3)
                    DO4H(hacc[1][4], hv1, wv4) DO4H(hacc[1][5], hv1, wv5)
                    DO4H(hacc[2][0], hv2, wv0) DO4H(hacc[2][1], hv2, wv1)
                    DO4H(hacc[2][2], hv2, wv2) DO4H(hacc[2][3], hv2, wv3)
                    DO4H(hacc[2][4], hv2, wv4) DO4H(hacc[2][5], hv2, wv5)
                    DO4H(hacc[3][0], hv3, wv0) DO4H(hacc[3][1], hv3, wv1)
                    DO4H(hacc[3][2], hv3, wv2) DO4H(hacc[3][3], hv3, wv3)
                    DO4H(hacc[3][4], hv3, wv4) DO4H(hacc[3][5], hv3, wv5)
                    if ((q & 7) == 7) {
#pragma unroll
                        for (int n = 0; n < 4; n++)
#pragma unroll
                            for (int r = 0; r < 6; r++) {
                                float2 f = __half22float2(hacc[n][r]);
                                facc[n][r] += f.x + f.y;
                                hacc[n][r] = __floats2half2_rn(0.f, 0.f);
                            }
                    }
                }
                // epilogue
#pragma unroll
                for (int n = 0; n < 4; n++) {
                    int m = 4 * ty + n;
                    int ordv = nd_s[m];
                    if (ordv < 0) continue;
                    int bb = ordv & 63, ii = ordv >> 6;
                    const float* awt = g_AW + (size_t)ts_s[m] * TH3;
                    const float* awp = aw_pe + (size_t)cp_s[m] * TH3;
                    float hnew[2];
#pragma unroll
                    for (int uu = 0; uu < 2; uu++) {
                        int u = c * 64 + 2 * tx + uu;
                        float gi_r = fmaf(4.f, awt[u], fmaf(0.25f, awp[u], bih_u[uu][0]));
                        float gi_z = fmaf(4.f, awt[256 + u], fmaf(0.25f, awp[256 + u], bih_u[uu][1]));
                        float gi_n = fmaf(4.f, awt[512 + u], fmaf(0.25f, awp[512 + u], bih_u[uu][2]));
                        float rg = sigmoid_fast(gi_r + facc[n][0 + uu] + bhh_u[uu][0]);
                        float zg = sigmoid_fast(gi_z + facc[n][2 + uu] + bhh_u[uu][1]);
                        float ng = tanh_fast(fmaf(rg, facc[n][4 + uu] + bhh_u[uu][2], gi_n));
                        float hp = h_s[m * 260 + u];
                        hnew[uu] = fmaf(zg, hp - ng, ng);
                    }
                    *(float2*)(out + ((size_t)ii * 64 + bb) * 512 + 256 + c * 64 + 2 * tx) =
                        make_float2(hnew[0], hnew[1]);
                }
            } else {
                // ---- M=16 gemv: warp = 1 node, thread = 6 rows ----
                int m = ty;   // 0..15
                float   facc[6];
                __half2 hacc[6];
#pragma unroll
                for (int r = 0; r < 6; r++) {
                    facc[r] = 0.f;
                    hacc[r] = __floats2half2_rn(0.f, 0.f);
                }
                const uint4* hp = (const uint4*)(h2_s + m * 132);
#pragma unroll
                for (int q = 0; q < 32; q++) {
                    uint4 hv = hp[q];
                    uint4 wv0 = wp[0][q], wv1 = wp[1][q], wv2 = wp[2][q];
                    uint4 wv3 = wp[3][q], wv4 = wp[4][q], wv5 = wp[5][q];
                    DO4H(hacc[0], hv, wv0) DO4H(hacc[1], hv, wv1)
                    DO4H(hacc[2], hv, wv2) DO4H(hacc[3], hv, wv3)
                    DO4H(hacc[4], hv, wv4) DO4H(hacc[5], hv, wv5)
                    if ((q & 7) == 7) {
#pragma unroll
                        for (int r = 0; r < 6; r++) {
                            float2 f = __half22float2(hacc[r]);
                            facc[r] += f.x + f.y;
                            hacc[r] = __floats2half2_rn(0.f, 0.f);
                        }
                    }
                }
                int ordv = nd_s[m];
                if (ordv >= 0) {
                    int bb = ordv & 63, ii = ordv >> 6;
                    const float* awt = g_AW + (size_t)ts_s[m] * TH3;
                    const float* awp = aw_pe + (size_t)cp_s[m] * TH3;
                    float hnew[2];
#pragma unroll
                    for (int uu = 0; uu < 2; uu++) {
                        int u = c * 64 + 2 * tx + uu;
                        float gi_r = fmaf(4.f, awt[u], fmaf(0.25f, awp[u], bih_u[uu][0]));
                        float gi_z = fmaf(4.f, awt[256 + u], fmaf(0.25f, awp[256 + u], bih_u[uu][1]));
                        float gi_n = fmaf(4.f, awt[512 + u], fmaf(0.25f, awp[512 + u], bih_u[uu][2]));
                        float rg = sigmoid_fast(gi_r + facc[0 + uu] + bhh_u[uu][0]);
                        float zg = sigmoid_fast(gi_z + facc[2 + uu] + bhh_u[uu][1]);
                        float ng = tanh_fast(fmaf(rg, facc[4 + uu] + bhh_u[uu][2], gi_n));
                        float hp = h_s[m * 260 + u];
                        hnew[uu] = fmaf(zg, hp - ng, ng);
                    }
                    *(float2*)(out + ((size_t)ii * 64 + bb) * 512 + 256 + c * 64 + 2 * tx) =
                        make_float2(hnew[0], hnew[1]);
                }
            }
        } // tiles

        // global wave barrier
        if (tid == 0) {
            __threadfence();
            int a = atomicAdd(&g_bar_cnt, 1);
            if (a == NCTA - 1) {
                atomicExch(&g_bar_cnt, 0);
                st_release_gpu(&g_bar_epoch, w + 1);
            } else {
                while (ld_acquire_gpu(&g_bar_epoch) < w + 1) { }
            }
        }
        __syncthreads();
    }
#undef DO4H
}

// ---------------------------------------------------------------------------
extern "C" void kernel_launch(void* const* d_in, const int* in_sizes, int n_in,
                              void* d_out, int out_size) {
    const int*   node_types = (const int*)d_in[0];
    const int*   node_vals  = (const int*)d_in[1];
    const int*   node_off   = (const int*)d_in[2];
    const int*   lpi        = (const int*)d_in[3];
    const int*   child_pos  = (const int*)d_in[4];
    const float* type_emb   = (const float*)d_in[5];
    const float* pos_table  = (const float*)d_in[6];
    const float* token_emb  = (const float*)d_in[7];
    const float* w_ih       = (const float*)d_in[8];
    const float* w_hh       = (const float*)d_in[9];
    const float* b_ih       = (const float*)d_in[10];
    const float* b_hh       = (const float*)d_in[11];
    float* out = (float*)d_out;
    int L = in_sizes[1];

    static int smem_set = 0;
    if (!smem_set) {
        cudaFuncSetAttribute(wave_gru_kernel,
                             cudaFuncAttributeMaxDynamicSharedMemorySize, WAVE_SMEM);
        smem_set = 1;
    }

    init_misc_kernel<<<1, 32>>>();
    aw_gemm_kernel<<<dim3(21, 12), 256>>>(type_emb, pos_table, w_ih);
    pack_whh_kernel<<<384, 256>>>(w_hh);
    prep_depth_kernel<<<64, 128>>>(lpi);
    prep_offsets_kernel<<<1, 1024>>>();
    prep_scatter_kernel<<<64, 128>>>();
    embed_out_kernel<<<16384, 256>>>(node_types, node_vals, node_off, child_pos,
                                     type_emb, pos_table, token_emb, out, L);
    wave_gru_kernel<<<NCTA, 512, WAVE_SMEM>>>(lpi, node_types, child_pos,
                                              b_ih, b_hh, out);
}

// round 15
// speedup vs baseline: 4.6794x; 1.0696x over previous
#include <cuda_runtime.h>
#include <cuda_fp16.h>

#define BB 64
#define NN 1024
#define TH3 768
#define NTYPES 300
#define AW_ROWS 1300

// ---- persistent device scratch (no runtime allocation) ----
__device__ float        g_AW[AW_ROWS * TH3];     // [type_emb;pos_table] @ w_ih^T
__device__ unsigned int g_whhp[TH3 * 128];       // w_hh half2, [row][k2]
__device__ int          g_depth[BB * NN];
__device__ int          g_cnt[BB * NN];          // [b][d]
__device__ int          g_batch_base[NN * BB];   // [d][b]
__device__ int          g_wave_off[NN + 1];
__device__ int          g_order[BB * NN];        // (i<<6)|b grouped by depth
__device__ int          g_nwaves;
__device__ int          g_bar_cnt;
__device__ int          g_bar_epoch;

__device__ __forceinline__ int ld_acquire_gpu(const int* p) {
    int v;
    asm volatile("ld.acquire.gpu.b32 %0, [%1];" : "=r"(v) : "l"(p) : "memory");
    return v;
}
__device__ __forceinline__ void st_release_gpu(int* p, int v) {
    asm volatile("st.release.gpu.b32 [%0], %1;" :: "l"(p), "r"(v) : "memory");
}
__device__ __forceinline__ float tanh_fast(float x) {
    float y;
    asm("tanh.approx.f32 %0, %1;" : "=f"(y) : "f"(x));
    return y;
}
__device__ __forceinline__ float sigmoid_fast(float x) {
    return 1.0f / (1.0f + __expf(-x));
}

// ---------------------------------------------------------------------------
__global__ void init_misc_kernel() {
    if (threadIdx.x == 0) { g_bar_cnt = 0; g_bar_epoch = 0; g_nwaves = 0; }
}

// ---------------------------------------------------------------------------
// g_AW[m][r] = dot(A_m, w_ih[r,:]),  A = concat(type_emb, pos_table), K=256
__global__ void aw_gemm_kernel(const float* __restrict__ te,
                               const float* __restrict__ pe,
                               const float* __restrict__ wih) {
    __shared__ float As[16][64];
    __shared__ float Ws[16][68];
    const int tx = threadIdx.x & 15;
    const int ty = threadIdx.x >> 4;
    float acc[4][4] = {};
    for (int kt = 0; kt < 256; kt += 16) {
        int row = threadIdx.x >> 2;
        int kk  = (threadIdx.x & 3) * 4;
        int m   = blockIdx.x * 64 + row;
        float4 av = make_float4(0.f, 0.f, 0.f, 0.f);
        if (m < AW_ROWS) {
            const float* ap = (m < NTYPES) ? (te + (size_t)m * 256)
                                           : (pe + (size_t)(m - NTYPES) * 256);
            av = *(const float4*)(ap + kt + kk);
        }
        As[kk + 0][row] = av.x; As[kk + 1][row] = av.y;
        As[kk + 2][row] = av.z; As[kk + 3][row] = av.w;
        float4 wv = *(const float4*)(wih + (size_t)(blockIdx.y * 64 + row) * 256 + kt + kk);
        Ws[kk + 0][row] = wv.x; Ws[kk + 1][row] = wv.y;
        Ws[kk + 2][row] = wv.z; Ws[kk + 3][row] = wv.w;
        __syncthreads();
#pragma unroll
        for (int k = 0; k < 16; k++) {
            float a[4], w[4];
#pragma unroll
            for (int i = 0; i < 4; i++) { a[i] = As[k][ty * 4 + i]; w[i] = Ws[k][tx * 4 + i]; }
#pragma unroll
            for (int i = 0; i < 4; i++)
#pragma unroll
                for (int j = 0; j < 4; j++)
                    acc[i][j] = fmaf(a[i], w[j], acc[i][j]);
        }
        __syncthreads();
    }
#pragma unroll
    for (int i = 0; i < 4; i++) {
        int m = blockIdx.x * 64 + ty * 4 + i;
        if (m < AW_ROWS) {
#pragma unroll
            for (int j = 0; j < 4; j++)
                g_AW[(size_t)m * TH3 + blockIdx.y * 64 + tx * 4 + j] = acc[i][j];
        }
    }
}

// ---------------------------------------------------------------------------
__global__ void pack_whh_kernel(const float* __restrict__ whh) {
    int idx = blockIdx.x * 256 + threadIdx.x;
    if (idx < 768 * 128) {
        int r  = idx >> 7;
        int k2 = idx & 127;
        __half2 h2 = __floats2half2_rn(whh[(size_t)r * 256 + 2 * k2],
                                       whh[(size_t)r * 256 + 2 * k2 + 1]);
        g_whhp[r * 128 + k2] = *(unsigned int*)&h2;
    }
}

// ---------------------------------------------------------------------------
__global__ void embed_out_kernel(const int* __restrict__ types,
                                 const int* __restrict__ vals,
                                 const int* __restrict__ offs,
                                 const int* __restrict__ cps,
                                 const float* __restrict__ te,
                                 const float* __restrict__ pe,
                                 const float* __restrict__ tok,
                                 float* __restrict__ out, int L) {
    int sub  = threadIdx.x >> 6;
    int lane = threadIdx.x & 63;
    int j = blockIdx.x * 4 + sub;
    int b = j >> 10, n = j & 1023;
    int tt  = types[j];
    int cp  = cps[j];
    int off = offs[j];
    int offn = (j + 1 < BB * NN) ? offs[j + 1] : L;
    float cnt = (float)((offn - off) > 1 ? (offn - off) : 1);
    float4 s = make_float4(0.f, 0.f, 0.f, 0.f);
    for (int v = off; v < offn; v++) {
        float4 t = ((const float4*)tok)[(size_t)vals[v] * 64 + lane];
        s.x += t.x; s.y += t.y; s.z += t.z; s.w += t.w;
    }
    float4 tev = ((const float4*)te)[(size_t)tt * 64 + lane];
    float4 pev = ((const float4*)pe)[(size_t)cp * 64 + lane];
    float inv = 4.0f / cnt;
    float4 r;
    r.x = 4.f * tev.x + 0.25f * pev.x + s.x * inv;
    r.y = 4.f * tev.y + 0.25f * pev.y + s.y * inv;
    r.z = 4.f * tev.z + 0.25f * pev.z + s.z * inv;
    r.w = 4.f * tev.w + 0.25f * pev.w + s.w * inv;
    ((float4*)out)[((size_t)n * 64 + b) * 128 + lane] = r;
}

// ---------------------------------------------------------------------------
// P1: per-batch node depth via wavefront relaxation + per-depth counts
__global__ void prep_depth_kernel(const int* __restrict__ lpi_all) {
    __shared__ int lpi_s[NN];
    __shared__ int dep_s[NN];
    __shared__ int cnt_s[NN];
    __shared__ int remain;
    int b = blockIdx.x, tid = threadIdx.x;
    for (int i = tid; i < NN; i += 256) {
        lpi_s[i] = lpi_all[b * NN + i];
        dep_s[i] = (i == 0) ? 0 : -1;
        cnt_s[i] = 0;
    }
    if (tid == 0) remain = NN - 1;
    __syncthreads();
    while (true) {
        if (remain == 0) break;
        int solved = 0;
        for (int i = tid; i < NN; i += 256) {
            if (dep_s[i] < 0) {
                int d = dep_s[lpi_s[i]];
                if (d >= 0) { dep_s[i] = d + 1; solved++; }
            }
        }
        __syncthreads();
        if (solved) atomicAdd(&remain, -solved);
        __syncthreads();
    }
    for (int i = tid; i < NN; i += 256) {
        atomicAdd(&cnt_s[dep_s[i]], 1);
        g_depth[b * NN + i] = dep_s[i];
    }
    __syncthreads();
    for (int d = tid; d < NN; d += 256) g_cnt[b * NN + d] = cnt_s[d];
}

// P2: per-depth batch prefixes + wave offsets (parallel scan) + wave count
__global__ void prep_offsets_kernel() {
    __shared__ int wsum[32];
    int d = threadIdx.x;           // 0..1023
    int lane = d & 31, wid = d >> 5;
    int base = 0;
    for (int b = 0; b < BB; b++) {
        g_batch_base[d * BB + b] = base;
        base += g_cnt[b * NN + d];
    }
    int v = base;                  // total nodes at depth d across batches
    // inclusive warp scan
    int pf = v;
#pragma unroll
    for (int o = 1; o < 32; o <<= 1) {
        int t = __shfl_up_sync(0xFFFFFFFFu, pf, o);
        if (lane >= o) pf += t;
    }
    if (lane == 31) wsum[wid] = pf;
    __syncthreads();
    if (wid == 0) {
        int s = wsum[lane];
        int inc = s;
#pragma unroll
        for (int o = 1; o < 32; o <<= 1) {
            int t = __shfl_up_sync(0xFFFFFFFFu, inc, o);
            if (lane >= o) inc += t;
        }
        wsum[lane] = inc - s;      // exclusive warp offset
    }
    __syncthreads();
    int excl = pf - v + wsum[wid];
    g_wave_off[d] = excl;
    if (d == NN - 1) g_wave_off[NN] = excl + v;
    if (v > 0) atomicMax(&g_nwaves, d + 1);
}

// P3: scatter nodes into wave order (parallel; intra-wave order irrelevant)
__global__ void prep_scatter_kernel() {
    __shared__ int cur_s[NN];
    int b = blockIdx.x, tid = threadIdx.x;
    for (int d = tid; d < NN; d += 256)
        cur_s[d] = g_wave_off[d] + g_batch_base[d * BB + b];
    __syncthreads();
    for (int i = tid; i < NN; i += 256) {
        int d = g_depth[b * NN + i];
        int pos = atomicAdd(&cur_s[d], 1);
        g_order[pos] = (i << 6) | b;
    }
}

// ---------------------------------------------------------------------------
// Wave GRU v4: 148 persistent CTAs = 37 node-groups x 4 chunk-CTAs, resident
// weights, ADAPTIVE tile height: per wave pick rounds r = ceil(W/2368), then
// nodes-per-thread NPT = ceil(W/(37*r*16)) in {1..4}, tile M = 16*NPT.
#define SM_W   0                      // w_s:  192*132 uints = 101376 B
#define SM_H2  101376                 // h2_s:  64*132 uints =  33792 B
#define SM_HF  135168                 // h_s:   64*260 floats =  66560 B
#define SM_ND  201728                 // node ids (64 ints)
#define SM_TS  201984
#define SM_CP  202240
#define WAVE_SMEM 202496
#define NCTA 148
#define NGRP 37

#define DO4H(ACC, HV, WV)                                                  \
    ACC = __hfma2(*(__half2*)&(WV).x, *(__half2*)&(HV).x, ACC);            \
    ACC = __hfma2(*(__half2*)&(WV).y, *(__half2*)&(HV).y, ACC);            \
    ACC = __hfma2(*(__half2*)&(WV).z, *(__half2*)&(HV).z, ACC);            \
    ACC = __hfma2(*(__half2*)&(WV).w, *(__half2*)&(HV).w, ACC);

template<int NPT>
__device__ __forceinline__ void process_tile(
    int base, int Mrem,
    const int* __restrict__ lpi_all, const int* __restrict__ types,
    const int* __restrict__ cps, float* __restrict__ out,
    unsigned int* h2_s, float* h_s, int* nd_s, int* ts_s, int* cp_s,
    const uint4* const* wp, const float* aw_pe,
    const float (&bih_u)[2][3], const float (&bhh_u)[2][3],
    int tid, int tx, int ty, int c)
{
    constexpr int Msz = 16 * NPT;
    __syncthreads();
    if (tid < Msz) {
        int ordv = -1, tt = 0, cpv = 0;
        if (tid < Mrem) {
            ordv = g_order[base + tid];
            int bb = ordv & 63, ii = ordv >> 6;
            tt  = types[bb * NN + ii];
            cpv = cps[bb * NN + ii];
        }
        nd_s[tid] = ordv; ts_s[tid] = tt; cp_s[tid] = cpv;
    }
    __syncthreads();

    // gather parent hidden states + half2 convert (coalesced, 64 f4/node)
#pragma unroll
    for (int it = 0; it < 2 * NPT; it++) {
        int f = tid + it * 512;
        int m = f >> 6, seg = f & 63;
        int ordv = nd_s[m];
        float4 v = make_float4(0.f, 0.f, 0.f, 0.f);
        if (ordv >= 0) {
            int bb = ordv & 63, ii = ordv >> 6;
            if (ii > 0) {
                int lp = lpi_all[bb * NN + ii];
                v = ((const float4*)(out + (((size_t)lp * 64 + bb) * 512 + 256)))[seg];
            }
        }
        *(float4*)(h_s + m * 260 + seg * 4) = v;
        __half2 a  = __floats2half2_rn(v.x, v.y);
        __half2 b2 = __floats2half2_rn(v.z, v.w);
        h2_s[m * 132 + seg * 2 + 0] = *(unsigned int*)&a;
        h2_s[m * 132 + seg * 2 + 1] = *(unsigned int*)&b2;
    }
    __syncthreads();

    // gemv: thread = NPT nodes x 6 rows
    float   facc[NPT][6];
    __half2 hacc[NPT][6];
#pragma unroll
    for (int n = 0; n < NPT; n++)
#pragma unroll
        for (int r = 0; r < 6; r++) {
            facc[n][r] = 0.f;
            hacc[n][r] = __floats2half2_rn(0.f, 0.f);
        }
    const uint4* hp[NPT];
#pragma unroll
    for (int n = 0; n < NPT; n++)
        hp[n] = (const uint4*)(h2_s + (NPT * ty + n) * 132);

#pragma unroll
    for (int q = 0; q < 32; q++) {
        uint4 wv0 = wp[0][q], wv1 = wp[1][q], wv2 = wp[2][q];
        uint4 wv3 = wp[3][q], wv4 = wp[4][q], wv5 = wp[5][q];
#pragma unroll
        for (int n = 0; n < NPT; n++) {
            uint4 hv = hp[n][q];
            DO4H(hacc[n][0], hv, wv0) DO4H(hacc[n][1], hv, wv1)
            DO4H(hacc[n][2], hv, wv2) DO4H(hacc[n][3], hv, wv3)
            DO4H(hacc[n][4], hv, wv4) DO4H(hacc[n][5], hv, wv5)
        }
        if ((q & 7) == 7) {
#pragma unroll
            for (int n = 0; n < NPT; n++)
#pragma unroll
                for (int r = 0; r < 6; r++) {
                    float2 f = __half22float2(hacc[n][r]);
                    facc[n][r] += f.x + f.y;
                    hacc[n][r] = __floats2half2_rn(0.f, 0.f);
                }
        }
    }

    // epilogue: gi gathers + gates + store
#pragma unroll
    for (int n = 0; n < NPT; n++) {
        int m = NPT * ty + n;
        int ordv = nd_s[m];
        if (ordv < 0) continue;
        int bb = ordv & 63, ii = ordv >> 6;
        const float* awt = g_AW + (size_t)ts_s[m] * TH3;
        const float* awp = aw_pe + (size_t)cp_s[m] * TH3;
        float hnew[2];
#pragma unroll
        for (int uu = 0; uu < 2; uu++) {
            int u = c * 64 + 2 * tx + uu;
            float gi_r = fmaf(4.f, awt[u], fmaf(0.25f, awp[u], bih_u[uu][0]));
            float gi_z = fmaf(4.f, awt[256 + u], fmaf(0.25f, awp[256 + u], bih_u[uu][1]));
            float gi_n = fmaf(4.f, awt[512 + u], fmaf(0.25f, awp[512 + u], bih_u[uu][2]));
            float rg = sigmoid_fast(gi_r + facc[n][0] * 0.f + facc[n][0 + uu] + bhh_u[uu][0]);
            float zg = sigmoid_fast(gi_z + facc[n][2 + uu] + bhh_u[uu][1]);
            float ng = tanh_fast(fmaf(rg, facc[n][4 + uu] + bhh_u[uu][2], gi_n));
            float hp_ = h_s[m * 260 + u];
            hnew[uu] = fmaf(zg, hp_ - ng, ng);
        }
        *(float2*)(out + ((size_t)ii * 64 + bb) * 512 + 256 + c * 64 + 2 * tx) =
            make_float2(hnew[0], hnew[1]);
    }
}

__global__ void __launch_bounds__(512, 1)
wave_gru_kernel(const int* __restrict__ lpi_all, const int* __restrict__ types,
                const int* __restrict__ cps, const float* __restrict__ bih,
                const float* __restrict__ bhh, float* __restrict__ out) {
    extern __shared__ unsigned char smem[];
    unsigned int* w_s  = (unsigned int*)(smem + SM_W);
    unsigned int* h2_s = (unsigned int*)(smem + SM_H2);
    float*        h_s  = (float*)(smem + SM_HF);
    int*          nd_s = (int*)(smem + SM_ND);
    int*          ts_s = (int*)(smem + SM_TS);
    int*          cp_s = (int*)(smem + SM_CP);

    const int tid = threadIdx.x;
    const int tx  = tid & 31;
    const int ty  = tid >> 5;
    const int c   = blockIdx.x & 3;       // chunk (64 hidden units) owned
    const int grp = blockIdx.x >> 2;      // node-group 0..36
    const int nwaves = g_nwaves;
    const float* aw_pe = g_AW + (size_t)NTYPES * TH3;

    // ---- load resident weight chunk once: 192 rows x 32 uint4, permuted ----
    {
        const uint4* src = (const uint4*)g_whhp;
#pragma unroll
        for (int it = 0; it < 12; it++) {
            int flat = tid + it * 512;       // 0..6143
            int slot = flat >> 5;            // 0..191
            int kq   = flat & 31;
            int g    = slot >> 6;
            int wi   = slot & 63;
            int j    = ((wi & 31) << 1) | (wi >> 5);
            int grow = g * 256 + c * 64 + j;
            *(uint4*)(w_s + slot * 132 + kq * 4) = src[grow * 32 + kq];
        }
    }
    float bih_u[2][3], bhh_u[2][3];
#pragma unroll
    for (int uu = 0; uu < 2; uu++)
#pragma unroll
        for (int g = 0; g < 3; g++) {
            int rr = g * 256 + c * 64 + 2 * tx + uu;
            bih_u[uu][g] = bih[rr];
            bhh_u[uu][g] = bhh[rr];
        }
    const uint4* wp[6];
#pragma unroll
    for (int g = 0; g < 3; g++)
#pragma unroll
        for (int uu = 0; uu < 2; uu++)
            wp[g * 2 + uu] = (const uint4*)(w_s + (g * 64 + tx + uu * 32) * 132);

    for (int w = 0; w < nwaves; w++) {
        int ms = g_wave_off[w];
        int me = g_wave_off[w + 1];
        int W  = me - ms;
        int r  = (W + NGRP * 64 - 1) / (NGRP * 64);       // rounds
        int npt = (W + NGRP * r * 16 - 1) / (NGRP * r * 16);
        if (npt < 1) npt = 1; if (npt > 4) npt = 4;
        int Msz = 16 * npt;
        int ntiles = (W + Msz - 1) / Msz;

        for (int t = grp; t < ntiles; t += NGRP) {
            int base = ms + t * Msz;
            int Mrem = me - base; if (Mrem > Msz) Mrem = Msz;
            switch (npt) {
            case 1: process_tile<1>(base, Mrem, lpi_all, types, cps, out, h2_s, h_s,
                                    nd_s, ts_s, cp_s, wp, aw_pe, bih_u, bhh_u,
                                    tid, tx, ty, c); break;
            case 2: process_tile<2>(base, Mrem, lpi_all, types, cps, out, h2_s, h_s,
                                    nd_s, ts_s, cp_s, wp, aw_pe, bih_u, bhh_u,
                                    tid, tx, ty, c); break;
            case 3: process_tile<3>(base, Mrem, lpi_all, types, cps, out, h2_s, h_s,
                                    nd_s, ts_s, cp_s, wp, aw_pe, bih_u, bhh_u,
                                    tid, tx, ty, c); break;
            default: process_tile<4>(base, Mrem, lpi_all, types, cps, out, h2_s, h_s,
                                     nd_s, ts_s, cp_s, wp, aw_pe, bih_u, bhh_u,
                                     tid, tx, ty, c); break;
            }
        }

        // global wave barrier
        if (tid == 0) {
            __threadfence();
            int a = atomicAdd(&g_bar_cnt, 1);
            if (a == NCTA - 1) {
                atomicExch(&g_bar_cnt, 0);
                st_release_gpu(&g_bar_epoch, w + 1);
            } else {
                while (ld_acquire_gpu(&g_bar_epoch) < w + 1) { }
            }
        }
        __syncthreads();
    }
}

// ---------------------------------------------------------------------------
extern "C" void kernel_launch(void* const* d_in, const int* in_sizes, int n_in,
                              void* d_out, int out_size) {
    const int*   node_types = (const int*)d_in[0];
    const int*   node_vals  = (const int*)d_in[1];
    const int*   node_off   = (const int*)d_in[2];
    const int*   lpi        = (const int*)d_in[3];
    const int*   child_pos  = (const int*)d_in[4];
    const float* type_emb   = (const float*)d_in[5];
    const float* pos_table  = (const float*)d_in[6];
    const float* token_emb  = (const float*)d_in[7];
    const float* w_ih       = (const float*)d_in[8];
    const float* w_hh       = (const float*)d_in[9];
    const float* b_ih       = (const float*)d_in[10];
    const float* b_hh       = (const float*)d_in[11];
    float* out = (float*)d_out;
    int L = in_sizes[1];

    static int smem_set = 0;
    if (!smem_set) {
        cudaFuncSetAttribute(wave_gru_kernel,
                             cudaFuncAttributeMaxDynamicSharedMemorySize, WAVE_SMEM);
        smem_set = 1;
    }

    init_misc_kernel<<<1, 32>>>();
    aw_gemm_kernel<<<dim3(21, 12), 256>>>(type_emb, pos_table, w_ih);
    pack_whh_kernel<<<384, 256>>>(w_hh);
    prep_depth_kernel<<<64, 256>>>(lpi);
    prep_offsets_kernel<<<1, 1024>>>();
    prep_scatter_kernel<<<64, 256>>>();
    embed_out_kernel<<<16384, 256>>>(node_types, node_vals, node_off, child_pos,
                                     type_emb, pos_table, token_emb, out, L);
    wave_gru_kernel<<<NCTA, 512, WAVE_SMEM>>>(lpi, node_types, child_pos,
                                              b_ih, b_hh, out);
}